// round 1
// baseline (speedup 1.0000x reference)
#include <cuda_runtime.h>
#include <math.h>

#define NT 8192
#define NC 8192
#define DIM 128
#define NTOT 16384

// ---------------- device globals (no cudaMalloc allowed) ----------------
__device__ float g_Xt[NT * DIM];
__device__ float g_Xc[NC * DIM];
__device__ float g_normT[NT];
__device__ float g_normC[NC];
__device__ int   g_it[NT];
__device__ int   g_ic[NC];
__device__ float g_M[(size_t)NT * NC];      // 256 MB distance matrix
__device__ float g_u[NT + 1];
__device__ float g_t[NC];
__device__ float g_s[NC + 1];
__device__ double g_sumM;
__device__ int    g_maxbits;
__device__ double g_dval;

struct Scal {
    float eff_lam, kd, delta;
    float sumS, sumU, sumV, vNC;
};
__device__ Scal g_sc;

// ---------------- split: ordered compaction of hal_label ----------------
__global__ void split_kernel(const int* __restrict__ hal) {
    __shared__ int wsum[32];
    int t = threadIdx.x;            // 1024 threads, 16 elems each
    int base = t * 16;
    int lab[16];
    int cnt = 0;
#pragma unroll
    for (int k = 0; k < 16; k++) { lab[k] = hal[base + k]; cnt += (lab[k] == 1); }
    int lane = t & 31, wid = t >> 5;
    int inc = cnt;
#pragma unroll
    for (int o = 1; o < 32; o <<= 1) {
        int y = __shfl_up_sync(0xffffffffu, inc, o);
        if (lane >= o) inc += y;
    }
    if (lane == 31) wsum[wid] = inc;
    __syncthreads();
    if (wid == 0) {
        int v = wsum[lane];
#pragma unroll
        for (int o = 1; o < 32; o <<= 1) {
            int y = __shfl_up_sync(0xffffffffu, v, o);
            if (lane >= o) v += y;
        }
        wsum[lane] = v;
    }
    __syncthreads();
    int excl = inc - cnt + (wid > 0 ? wsum[wid - 1] : 0);
    int tpos = excl;
#pragma unroll
    for (int k = 0; k < 16; k++) {
        int i = base + k;
        if (lab[k] == 1) g_it[tpos++] = i;
        else             g_ic[i - tpos] = i;
    }
}

// ---------------- gather rows + squared norms ----------------
__global__ void gather_kernel(const float* __restrict__ X) {
    int b = blockIdx.x, t = threadIdx.x;   // 128 threads
    int src, r;
    if (b < NT) { r = b;      src = g_it[r]; }
    else        { r = b - NT; src = g_ic[r]; }
    float v = X[(size_t)src * DIM + t];
    if (b < NT) g_Xt[(size_t)r * DIM + t] = v;
    else        g_Xc[(size_t)r * DIM + t] = v;
    float sq = v * v;
#pragma unroll
    for (int o = 16; o > 0; o >>= 1) sq += __shfl_down_sync(0xffffffffu, sq, o);
    __shared__ float ws[4];
    if ((t & 31) == 0) ws[t >> 5] = sq;
    __syncthreads();
    if (t == 0) {
        float s = ws[0] + ws[1] + ws[2] + ws[3];
        if (b < NT) g_normT[r] = s; else g_normC[r] = s;
    }
}

__global__ void zero_misc_kernel() {
    g_sumM = 0.0;
    g_maxbits = 0;
    g_dval = 0.0;
}

// ---------------- GEMM + distances + stats ----------------
__global__ __launch_bounds__(256) void gemm_dist_kernel() {
    __shared__ float As[16][132];
    __shared__ float Bs[16][132];
    int bx = blockIdx.x, by = blockIdx.y;
    int tid = threadIdx.x;
    int tx = tid & 15, ty = tid >> 4;
    float acc[8][8];
#pragma unroll
    for (int i = 0; i < 8; i++)
#pragma unroll
        for (int j = 0; j < 8; j++) acc[i][j] = 0.f;

    const float* A = g_Xt + (size_t)by * 128 * DIM;
    const float* B = g_Xc + (size_t)bx * 128 * DIM;
    int lr = tid >> 2, lk = (tid & 3) * 4;

#pragma unroll 1
    for (int kk = 0; kk < DIM; kk += 16) {
        float4 a0 = *(const float4*)(A + lr * DIM + kk + lk);
        float4 a1 = *(const float4*)(A + (lr + 64) * DIM + kk + lk);
        float4 b0 = *(const float4*)(B + lr * DIM + kk + lk);
        float4 b1 = *(const float4*)(B + (lr + 64) * DIM + kk + lk);
        __syncthreads();
        As[lk + 0][lr] = a0.x; As[lk + 1][lr] = a0.y; As[lk + 2][lr] = a0.z; As[lk + 3][lr] = a0.w;
        As[lk + 0][lr + 64] = a1.x; As[lk + 1][lr + 64] = a1.y; As[lk + 2][lr + 64] = a1.z; As[lk + 3][lr + 64] = a1.w;
        Bs[lk + 0][lr] = b0.x; Bs[lk + 1][lr] = b0.y; Bs[lk + 2][lr] = b0.z; Bs[lk + 3][lr] = b0.w;
        Bs[lk + 0][lr + 64] = b1.x; Bs[lk + 1][lr + 64] = b1.y; Bs[lk + 2][lr + 64] = b1.z; Bs[lk + 3][lr + 64] = b1.w;
        __syncthreads();
#pragma unroll
        for (int k = 0; k < 16; k++) {
            float ar[8], br[8];
#pragma unroll
            for (int i = 0; i < 8; i++) ar[i] = As[k][ty * 8 + i];
#pragma unroll
            for (int j = 0; j < 8; j++) br[j] = Bs[k][tx * 8 + j];
#pragma unroll
            for (int i = 0; i < 8; i++)
#pragma unroll
                for (int j = 0; j < 8; j++) acc[i][j] = fmaf(ar[i], br[j], acc[i][j]);
        }
    }

    int m0 = by * 128 + ty * 8, n0 = bx * 128 + tx * 8;
    float nT[8], nC[8];
#pragma unroll
    for (int i = 0; i < 8; i++) { nT[i] = g_normT[m0 + i]; nC[i] = g_normC[n0 + i]; }

    double lsum = 0.0; float lmax = 0.f;
#pragma unroll
    for (int i = 0; i < 8; i++) {
        float4 o2[2];
#pragma unroll
        for (int j = 0; j < 8; j++) {
            float sq = nT[i] + nC[j] - 2.0f * acc[i][j];
            float d = sqrtf(fmaxf(sq, 1e-10f));
            ((float*)o2)[j] = d;
            lsum += (double)d;
            lmax = fmaxf(lmax, d);
        }
        float4* dst = (float4*)(g_M + (size_t)(m0 + i) * NC + n0);
        dst[0] = o2[0]; dst[1] = o2[1];
    }

    __shared__ double rs[256];
    __shared__ float rm[256];
    rs[tid] = lsum; rm[tid] = lmax;
    __syncthreads();
    for (int o = 128; o > 0; o >>= 1) {
        if (tid < o) { rs[tid] += rs[tid + o]; rm[tid] = fmaxf(rm[tid], rm[tid + o]); }
        __syncthreads();
    }
    if (tid == 0) {
        atomicAdd(&g_sumM, rs[0]);
        atomicMax(&g_maxbits, __float_as_int(rm[0]));
    }
}

// ---------------- scalar prep ----------------
__global__ void prep_kernel() {
    float mean = (float)(g_sumM / ((double)NT * (double)NC));
    float lam = 10.0f / mean;
    float delta = __int_as_float(g_maxbits);
    g_sc.eff_lam = lam;
    g_sc.delta = delta;
    g_sc.kd = __expf(-lam * delta) + 1e-6f;
}

__global__ void init_u_kernel() {
    int i = blockIdx.x * blockDim.x + threadIdx.x;
    if (i < NT) g_u[i] = 0.5f / (float)NT;
    else if (i == NT) g_u[NT] = 0.5f;
}

__global__ void zero_t_kernel() {
    int i = blockIdx.x * blockDim.x + threadIdx.x;
    if (i < NC) g_t[i] = 0.f;
}

// ---------------- column matvec: t[j] += sum_i exp(-lam*M[i,j]) * u[i] ----------------
__global__ __launch_bounds__(256) void colmv_kernel() {
    __shared__ float su[256];
    int col = blockIdx.x * 256 + threadIdx.x;
    int r0 = blockIdx.y * 256;
    su[threadIdx.x] = g_u[r0 + threadIdx.x];
    __syncthreads();
    float lam = g_sc.eff_lam;
    float acc = 0.f;
    const float* Mp = g_M + (size_t)r0 * NC + col;
#pragma unroll 4
    for (int r = 0; r < 256; r++) {
        acc += __expf(-lam * Mp[(size_t)r * NC]) * su[r];
    }
    atomicAdd(&g_t[col], acc);
}

// ---------------- scalar column step: s = b / t_full, slack + sums ----------------
__device__ __forceinline__ float block_reduce_f(float v, float* red) {
    int t = threadIdx.x, lane = t & 31, wid = t >> 5;
#pragma unroll
    for (int o = 16; o > 0; o >>= 1) v += __shfl_down_sync(0xffffffffu, v, o);
    if (lane == 0) red[wid] = v;
    __syncthreads();
    if (wid == 0) {
        float r = red[lane];
#pragma unroll
        for (int o = 16; o > 0; o >>= 1) r += __shfl_down_sync(0xffffffffu, r, o);
        if (lane == 0) red[0] = r;
    }
    __syncthreads();
    float out = red[0];
    __syncthreads();
    return out;
}

__global__ __launch_bounds__(1024) void scol_kernel(int update_u) {
    __shared__ float red[32];
    __shared__ float s_addc, s_sNC, s_sumU;
    int t = threadIdx.x;

    float su = 0.f;
    for (int i = t; i < NT; i += 1024) su += g_u[i];
    float sumU = block_reduce_f(su, red);

    if (t == 0) {
        float uN = g_u[NT];
        float kd = g_sc.kd;
        s_sumU = sumU;
        s_addc = 1e-6f * sumU + kd * uN;                       // constant added to all t[j]
        float tNC = kd * sumU + (1.0f + 1e-6f) * uN;           // slack column of K^T u
        s_sNC = 0.5f / tNC;                                    // b[NC] = p = 0.5
    }
    __syncthreads();

    float addc = s_addc;
    const float binv = 0.5f / (float)NC;                       // b[j] = (1-p)/NC
    float ssum = 0.f;
    for (int j = t; j < NC; j += 1024) {
        float sv = binv / (g_t[j] + addc);
        g_s[j] = sv;
        ssum += sv;
    }
    float sumS = block_reduce_f(ssum, red);

    if (t == 0) {
        g_s[NC] = s_sNC;
        g_sc.sumS = sumS;
        g_sc.sumU = s_sumU;
        if (update_u) {
            // u[NT] = a[NT] / (K[NT,:] @ s)
            g_u[NT] = 0.5f / (g_sc.kd * sumS + (1.0f + 1e-6f) * s_sNC);
        } else {
            g_sc.sumV = sumS;
            g_sc.vNC = s_sNC;
        }
    }
}

// ---------------- row matvec: u[i] = a_i / (sum_j K[i,j]*s[j]) ----------------
__global__ __launch_bounds__(256) void rowmv_kernel() {
    __shared__ float ss[NC];
    __shared__ float red[8];
    int t = threadIdx.x;
    for (int j = t; j < NC; j += 256) ss[j] = g_s[j];
    __syncthreads();
    float lam = g_sc.eff_lam;
    float add = 1e-6f * g_sc.sumS + g_sc.kd * g_s[NC];
    const float au = 0.5f / (float)NT;
    for (int r = 0; r < 8; r++) {
        int row = blockIdx.x * 8 + r;
        const float* Mp = g_M + (size_t)row * NC;
        float acc = 0.f;
        for (int c = t; c < NC; c += 256) acc += __expf(-lam * Mp[c]) * ss[c];
#pragma unroll
        for (int o = 16; o > 0; o >>= 1) acc += __shfl_down_sync(0xffffffffu, acc, o);
        if ((t & 31) == 0) red[t >> 5] = acc;
        __syncthreads();
        if (t == 0) {
            float tot = red[0] + red[1] + red[2] + red[3] + red[4] + red[5] + red[6] + red[7];
            g_u[row] = au / (tot + add);
        }
        __syncthreads();
    }
}

// ---------------- final: sum of T .* Mt over main block ----------------
__global__ __launch_bounds__(256) void final_kernel() {
    __shared__ float vv[NC];
    __shared__ double red[8];
    int t = threadIdx.x;
    for (int j = t; j < NC; j += 256) vv[j] = g_s[j];
    __syncthreads();
    float lam = g_sc.eff_lam;
    double lsum = 0.0;
    for (int r = 0; r < 8; r++) {
        int row = blockIdx.x * 8 + r;
        const float* Mp = g_M + (size_t)row * NC;
        float u = g_u[row];
        float acc = 0.f;
        for (int c = t; c < NC; c += 256) {
            float m = Mp[c];
            acc += (__expf(-lam * m) + 1e-6f) * m * vv[c];
        }
        lsum += (double)u * (double)acc;
    }
#pragma unroll
    for (int o = 16; o > 0; o >>= 1) lsum += __shfl_down_sync(0xffffffffu, lsum, o);
    if ((t & 31) == 0) red[t >> 5] = lsum;
    __syncthreads();
    if (t == 0) {
        double tot = red[0] + red[1] + red[2] + red[3] + red[4] + red[5] + red[6] + red[7];
        atomicAdd(&g_dval, tot);
    }
}

__global__ void write_kernel(float* out) {
    double mainsum = g_dval;
    double delta = (double)g_sc.delta;
    double kd = (double)g_sc.kd;
    // slack column: i<NT, j=NC : sum_i u_i*kd*v_NC*delta
    double sc = delta * kd * (double)g_sc.vNC * (double)g_sc.sumU;
    // slack row: i=NT, j<NC : sum_j u_NT*kd*v_j*delta
    double sr = delta * kd * (double)g_u[NT] * (double)g_sc.sumV;
    out[0] = (float)(2.0 * (mainsum + sc + sr));
}

// ---------------- launch ----------------
extern "C" void kernel_launch(void* const* d_in, const int* in_sizes, int n_in,
                              void* d_out, int out_size) {
    (void)in_sizes; (void)n_in; (void)out_size;
    const float* X = (const float*)d_in[0];
    const int* hal = (const int*)d_in[1];
    float* out = (float*)d_out;

    split_kernel<<<1, 1024>>>(hal);
    gather_kernel<<<NTOT, 128>>>(X);
    zero_misc_kernel<<<1, 1>>>();
    gemm_dist_kernel<<<dim3(NC / 128, NT / 128), 256>>>();
    prep_kernel<<<1, 1>>>();
    init_u_kernel<<<33, 256>>>();

    for (int it = 0; it < 10; ++it) {
        zero_t_kernel<<<32, 256>>>();
        colmv_kernel<<<dim3(NC / 256, NT / 256), 256>>>();
        scol_kernel<<<1, 1024>>>(1);
        rowmv_kernel<<<NT / 8, 256>>>();
    }

    // v = b / (K^T u) with final u; no u update
    zero_t_kernel<<<32, 256>>>();
    colmv_kernel<<<dim3(NC / 256, NT / 256), 256>>>();
    scol_kernel<<<1, 1024>>>(0);

    final_kernel<<<NT / 8, 256>>>();
    write_kernel<<<1, 1>>>(out);
}